// round 13
// baseline (speedup 1.0000x reference)
#include <cuda_runtime.h>
#include <cstdint>
#include <cmath>

#define T_SEQ   4096
#define TAGS    24
#define START_T 22
#define STOP_T  23
#define NEGV    (-10000.0f)

#define NCTA_DIR    32
#define REC_THREADS 512

// ---------------- scratch (device globals; no cudaMalloc allowed) ----------
__device__ float    g_xg[(size_t)T_SEQ * 4096];   // [t][dir*2048 + gate*512 + cell]
__device__ float    g_lstm[(size_t)T_SEQ * 1024]; // [t][dir*512 + cell]
__device__ float    g_feats[T_SEQ * TAGS];
// h exchange: one 8B word per cell = (tag<<32 | fp32 bits). Tag==s+1 for the h
// that is INPUT to step s; double-buffered by step parity. STRONG acquire/
// release ops: weak 64b accesses carry no formal atomicity/visibility
// guarantee (R12 lesson).
__device__ unsigned long long g_hx[2][2][512];    // [dir][parity][cell]

__device__ __forceinline__ unsigned long long ld_acq64(const unsigned long long* p)
{
    unsigned long long v;
    asm volatile("ld.acquire.gpu.global.u64 %0, [%1];" : "=l"(v) : "l"(p) : "memory");
    return v;
}
__device__ __forceinline__ void st_rel64(unsigned long long* p, unsigned long long v)
{
    asm volatile("st.release.gpu.global.u64 [%0], %1;" :: "l"(p), "l"(v) : "memory");
}
__device__ __forceinline__ unsigned long long pack_ht(float h, unsigned tag)
{
    return ((unsigned long long)tag << 32) | (unsigned long long)__float_as_uint(h);
}

#define FMA2(d, a, b, c) \
    asm("fma.rn.f32x2 %0, %1, %2, %3;" : "=l"(d) : "l"(a), "l"(b), "l"(c))

// ---------------- kernel 1: fused gather + input-projection GEMM -----------
__global__ void proj_gemm(const int* __restrict__ sent, const float* __restrict__ emb,
                          const float* __restrict__ wf, const float* __restrict__ wb,
                          const float* __restrict__ bihf, const float* __restrict__ bhhf,
                          const float* __restrict__ bihb, const float* __restrict__ bhhb)
{
    __shared__ __align__(16) float As[32][68];
    __shared__ __align__(16) float Bs[32][68];
    __shared__ int toks[64];

    const int tid = threadIdx.x;          // 0..255
    const int m0 = blockIdx.y * 64;
    const int n0 = blockIdx.x * 64;
    if (tid < 64) toks[tid] = sent[m0 + tid];
    __syncthreads();

    const int ty = tid >> 4;
    const int tx = tid & 15;

    float acc[4][4];
#pragma unroll
    for (int i = 0; i < 4; i++)
#pragma unroll
        for (int j = 0; j < 4; j++) acc[i][j] = 0.f;

    for (int k0 = 0; k0 < 512; k0 += 32) {
#pragma unroll
        for (int r = 0; r < 2; r++) {
            int idx = tid + r * 256;
            int row = idx >> 3;
            int kq  = idx & 7;
            float4 a = *(const float4*)(emb + (size_t)toks[row] * 512 + k0 + kq * 4);
            As[kq*4+0][row] = a.x; As[kq*4+1][row] = a.y;
            As[kq*4+2][row] = a.z; As[kq*4+3][row] = a.w;
            int n = n0 + row;
            const float* wsrc = (n < 2048) ? (wf + (size_t)n * 512)
                                           : (wb + (size_t)(n - 2048) * 512);
            float4 b = *(const float4*)(wsrc + k0 + kq * 4);
            Bs[kq*4+0][row] = b.x; Bs[kq*4+1][row] = b.y;
            Bs[kq*4+2][row] = b.z; Bs[kq*4+3][row] = b.w;
        }
        __syncthreads();
#pragma unroll
        for (int kk = 0; kk < 32; kk++) {
            float4 aa = *(const float4*)&As[kk][ty * 4];
            float4 bb = *(const float4*)&Bs[kk][tx * 4];
            float av[4] = {aa.x, aa.y, aa.z, aa.w};
            float bv[4] = {bb.x, bb.y, bb.z, bb.w};
#pragma unroll
            for (int i = 0; i < 4; i++)
#pragma unroll
                for (int j = 0; j < 4; j++) acc[i][j] += av[i] * bv[j];
        }
        __syncthreads();
    }

#pragma unroll
    for (int i = 0; i < 4; i++) {
        int m = m0 + ty * 4 + i;
        float* orow = g_xg + (size_t)m * 4096 + n0 + tx * 4;
#pragma unroll
        for (int j = 0; j < 4; j++) {
            int n = n0 + tx * 4 + j;
            float bias = (n < 2048) ? (bihf[n] + bhhf[n])
                                    : (bihb[n - 2048] + bhhb[n - 2048]);
            orow[j] = acc[i][j] + bias;
        }
    }
}

// ---------------- kernel 2: persistent BiLSTM recurrence -------------------
// 64 CTAs (32/dir), 512 threads (16 warps). Warp w owns cell 16r+w entirely:
// lane l = gate (l>>3), k-slice [(l&7)*64, +64), weights f32x2 in REGISTERS.
// Per step: cooperative acquire-poll (1 word/lane) -> stage hsm -> barrier ->
// per-warp dot + shfl reduce -> lane0 gates + release-publish -> barrier.
__global__ void __launch_bounds__(REC_THREADS, 1)
lstm_rec(const float* __restrict__ whf, const float* __restrict__ whb,
         const float* __restrict__ h0, const float* __restrict__ c0)
{
    const int cta = blockIdx.x;       // 0..63
    const int d   = cta >> 5;
    const int r   = cta & 31;         // owns cells [16r, 16r+16)
    const int tid = threadIdx.x;
    const int w   = tid >> 5;         // warp 0..15 -> cell
    const int l   = tid & 31;
    const int gate = l >> 3;
    const int ks   = l & 7;           // k-slice id
    const int cell = (r << 4) + w;
    const int row  = gate * 512 + cell;

    const float* whh = d ? whb : whf;

    // ---- weights -> registers, packed f32x2 (one-time) ----
    unsigned long long W2[32];
    {
        const float2* wp = (const float2*)(whh + (size_t)row * 512 + ks * 64);
#pragma unroll
        for (int i = 0; i < 32; i++) {
            float2 v = wp[i];
            W2[i] = ((unsigned long long)__float_as_uint(v.y) << 32)
                  | (unsigned long long)__float_as_uint(v.x);
        }
    }

    __shared__ __align__(16) float hsm[2][512];   // parity-buffered staged h

    float cst = 0.f;
    if (l == 0) {
        cst = c0[d * 512 + cell];
        st_rel64(&g_hx[d][0][cell], pack_ht(h0[d * 512 + cell], 1u));
    }

    for (int s = 0; s < T_SEQ; s++) {
        const int t = d ? (T_SEQ - 1 - s) : s;

        // xg prefetch (independent of h); same value across the 8-lane group
        float xv = __ldcg(&g_xg[(size_t)t * 4096 + d * 2048 + row]);

        // ---- cooperative poll: warp w polls cells [32w, 32w+32), 1/lane ----
        {
            const unsigned want = (unsigned)(s + 1);
            const unsigned long long* p = &g_hx[d][s & 1][(w << 5) + l];
            unsigned long long v;
            do { v = ld_acq64(p); } while ((unsigned)(v >> 32) != want);
            hsm[s & 1][(w << 5) + l] = __uint_as_float((unsigned)v);
        }
        __syncthreads();

        // ---- dot: packed f32x2 FMA over this lane's 64-wide k-slice ----
        const ulonglong2* hv = (const ulonglong2*)&hsm[s & 1][ks << 6];
        unsigned long long a0 = 0ull, a1 = 0ull;
#pragma unroll
        for (int i = 0; i < 16; i++) {
            ulonglong2 h2 = hv[i];   // broadcast LDS within 8-lane group
            FMA2(a0, W2[2 * i],     h2.x, a0);
            FMA2(a1, W2[2 * i + 1], h2.y, a1);
        }
        float p0 = __uint_as_float((unsigned)a0) + __uint_as_float((unsigned)(a0 >> 32));
        float p1 = __uint_as_float((unsigned)a1) + __uint_as_float((unsigned)(a1 >> 32));
        float a = p0 + p1;
        // k-reduce across the 8-lane group (same tree as R11: bit-identical)
        a += __shfl_xor_sync(0xffffffffu, a, 1);
        a += __shfl_xor_sync(0xffffffffu, a, 2);
        a += __shfl_xor_sync(0xffffffffu, a, 4);
        a += xv;
        // gather the four gate sums of this cell into lane 0
        float fg = __shfl_sync(0xffffffffu, a, 8);
        float gg = __shfl_sync(0xffffffffu, a, 16);
        float ov = __shfl_sync(0xffffffffu, a, 24);
        if (l == 0) {
            float iv = 1.f / (1.f + expf(-a));
            fg = 1.f / (1.f + expf(-fg));
            gg = tanhf(gg);
            ov = 1.f / (1.f + expf(-ov));
            cst = fg * cst + iv * gg;
            float hn = ov * tanhf(cst);
            st_rel64(&g_hx[d][(s + 1) & 1][cell], pack_ht(hn, (unsigned)(s + 2)));
            __stcg(&g_lstm[(size_t)t * 1024 + d * 512 + cell], hn);
        }
        __syncthreads();   // defense-in-depth: closes every intra-CTA window
    }
}

// ---------------- kernel 3: tag features -----------------------------------
__global__ void feats_k(const float* __restrict__ wtag, const float* __restrict__ btag)
{
    const int t = blockIdx.x;
    const int w = threadIdx.x >> 5;
    const int lane = threadIdx.x & 31;

    const float4* lx = (const float4*)(g_lstm + (size_t)t * 1024 + lane * 32);
    float4 X[8];
#pragma unroll
    for (int i = 0; i < 8; i++) X[i] = lx[i];

#pragma unroll
    for (int rep = 0; rep < 3; rep++) {
        int tag = w + rep * 8;
        const float4* wt = (const float4*)(wtag + (size_t)tag * 1024 + lane * 32);
        float a = 0.f;
#pragma unroll
        for (int i = 0; i < 8; i++) {
            float4 v = wt[i];
            a += X[i].x * v.x + X[i].y * v.y + X[i].z * v.z + X[i].w * v.w;
        }
#pragma unroll
        for (int o = 16; o; o >>= 1) a += __shfl_xor_sync(0xffffffffu, a, o);
        if (lane == 0) g_feats[t * TAGS + tag] = a + btag[tag];
    }
}

// ---------------- kernel 4: Viterbi (1 warp, bp in smem) -------------------
__global__ void viterbi_k(const float* __restrict__ trans, float* __restrict__ out,
                          int out_size)
{
    extern __shared__ unsigned char bp[];      // T_SEQ * TAGS bytes
    __shared__ float trs[TAGS * 25];
    __shared__ float stopr[TAGS];

    const int lane = threadIdx.x;
    for (int i = lane; i < TAGS * TAGS; i += 32) {
        int n = i / TAGS, p = i % TAGS;
        trs[n * 25 + p] = trans[i];
    }
    if (lane < TAGS) stopr[lane] = trans[STOP_T * TAGS + lane];
    __syncwarp();

    float fv = (lane == START_T) ? 0.f : NEGV;
    float feat = (lane < TAGS) ? g_feats[lane] : 0.f;

    for (int t = 0; t < T_SEQ; t++) {
        float nf = (lane < TAGS && t + 1 < T_SEQ) ? g_feats[(t + 1) * TAGS + lane] : 0.f;
        float best = -3.4e38f;
        int bi = 0;
#pragma unroll
        for (int p = 0; p < TAGS; p++) {
            float src = __shfl_sync(0xffffffffu, fv, p);
            float v = src + ((lane < TAGS) ? trs[lane * 25 + p] : 0.f);
            if (v > best) { best = v; bi = p; }
        }
        if (lane < TAGS) {
            fv = best + feat;
            bp[t * TAGS + lane] = (unsigned char)bi;
        } else {
            fv = NEGV;
        }
        feat = nf;
    }

    float ttl = (lane < TAGS) ? fv + stopr[lane] : -3.4e38f;
    float bv = ttl; int bi = lane;
#pragma unroll
    for (int o = 16; o; o >>= 1) {
        float ov = __shfl_down_sync(0xffffffffu, bv, o);
        int   oi = __shfl_down_sync(0xffffffffu, bi, o);
        if (ov > bv || (ov == bv && oi < bi)) { bv = ov; bi = oi; }
    }

    if (lane == 0) {
        float score = bv;
        int cur = bi;
        if (out_size >= T_SEQ + 1) {
            out[0] = score;
            float* path = out + 1;
            path[T_SEQ - 1] = (float)cur;
            for (int t = T_SEQ - 1; t >= 1; t--) {
                cur = bp[t * TAGS + cur];
                path[t - 1] = (float)cur;
            }
        } else if (out_size == T_SEQ) {
            out[T_SEQ - 1] = (float)cur;
            for (int t = T_SEQ - 1; t >= 1; t--) {
                cur = bp[t * TAGS + cur];
                out[t - 1] = (float)cur;
            }
        } else {
            out[0] = score;
        }
    }
}

// ---------------- launcher --------------------------------------------------
extern "C" void kernel_launch(void* const* d_in, const int* in_sizes, int n_in,
                              void* d_out, int out_size)
{
    const int*   sent  = (const int*)  d_in[0];
    const float* emb   = (const float*)d_in[1];
    const float* wihf  = (const float*)d_in[2];
    const float* whhf  = (const float*)d_in[3];
    const float* bihf  = (const float*)d_in[4];
    const float* bhhf  = (const float*)d_in[5];
    const float* wihb  = (const float*)d_in[6];
    const float* whhb  = (const float*)d_in[7];
    const float* bihb  = (const float*)d_in[8];
    const float* bhhb  = (const float*)d_in[9];
    const float* wtag  = (const float*)d_in[10];
    const float* btag  = (const float*)d_in[11];
    const float* trans = (const float*)d_in[12];
    const float* h0    = (const float*)d_in[13];
    const float* c0    = (const float*)d_in[14];
    float* out = (float*)d_out;

    proj_gemm<<<dim3(64, 64), 256>>>(sent, emb, wihf, wihb, bihf, bhhf, bihb, bhhb);
    lstm_rec<<<2 * NCTA_DIR, REC_THREADS>>>(whhf, whhb, h0, c0);
    feats_k<<<T_SEQ, 256>>>(wtag, btag);

    cudaFuncSetAttribute(viterbi_k, cudaFuncAttributeMaxDynamicSharedMemorySize,
                         T_SEQ * TAGS);
    viterbi_k<<<1, 32, T_SEQ * TAGS>>>(trans, out, out_size);
}

// round 14
// speedup vs baseline: 1.2742x; 1.2742x over previous
#include <cuda_runtime.h>
#include <cstdint>
#include <cmath>

#define T_SEQ   4096
#define TAGS    24
#define START_T 22
#define STOP_T  23
#define NEGV    (-10000.0f)

#define NCTA_DIR    64
#define REC_THREADS 256

// ---------------- scratch (device globals; no cudaMalloc allowed) ----------
__device__ float    g_xg[(size_t)T_SEQ * 4096];   // [t][dir*2048 + gate*512 + cell]
__device__ float    g_lstm[(size_t)T_SEQ * 1024]; // [t][dir*512 + cell]
__device__ float    g_feats[T_SEQ * TAGS];
// h exchange: one 8B word per cell = (tag<<32 | fp32 bits). Tag==s+1 for the h
// that is INPUT to step s; double-buffered by step parity. STRONG acquire/
// release ops only (R12 lesson: weak 64b has no atomicity guarantee).
__device__ unsigned long long g_hx[2][2][512];    // [dir][parity][cell]

__device__ __forceinline__ unsigned long long ld_acq64(const unsigned long long* p)
{
    unsigned long long v;
    asm volatile("ld.acquire.gpu.global.u64 %0, [%1];" : "=l"(v) : "l"(p) : "memory");
    return v;
}
__device__ __forceinline__ void st_rel64(unsigned long long* p, unsigned long long v)
{
    asm volatile("st.release.gpu.global.u64 [%0], %1;" :: "l"(p), "l"(v) : "memory");
}
__device__ __forceinline__ unsigned long long pack_ht(float h, unsigned tag)
{
    return ((unsigned long long)tag << 32) | (unsigned long long)__float_as_uint(h);
}

#define FMA2(d, a, b, c) \
    asm("fma.rn.f32x2 %0, %1, %2, %3;" : "=l"(d) : "l"(a), "l"(b), "l"(c))

// ---------------- kernel 1: fused gather + input-projection GEMM -----------
__global__ void proj_gemm(const int* __restrict__ sent, const float* __restrict__ emb,
                          const float* __restrict__ wf, const float* __restrict__ wb,
                          const float* __restrict__ bihf, const float* __restrict__ bhhf,
                          const float* __restrict__ bihb, const float* __restrict__ bhhb)
{
    __shared__ __align__(16) float As[32][68];
    __shared__ __align__(16) float Bs[32][68];
    __shared__ int toks[64];

    const int tid = threadIdx.x;          // 0..255
    const int m0 = blockIdx.y * 64;
    const int n0 = blockIdx.x * 64;
    if (tid < 64) toks[tid] = sent[m0 + tid];
    __syncthreads();

    const int ty = tid >> 4;
    const int tx = tid & 15;

    float acc[4][4];
#pragma unroll
    for (int i = 0; i < 4; i++)
#pragma unroll
        for (int j = 0; j < 4; j++) acc[i][j] = 0.f;

    for (int k0 = 0; k0 < 512; k0 += 32) {
#pragma unroll
        for (int r = 0; r < 2; r++) {
            int idx = tid + r * 256;
            int row = idx >> 3;
            int kq  = idx & 7;
            float4 a = *(const float4*)(emb + (size_t)toks[row] * 512 + k0 + kq * 4);
            As[kq*4+0][row] = a.x; As[kq*4+1][row] = a.y;
            As[kq*4+2][row] = a.z; As[kq*4+3][row] = a.w;
            int n = n0 + row;
            const float* wsrc = (n < 2048) ? (wf + (size_t)n * 512)
                                           : (wb + (size_t)(n - 2048) * 512);
            float4 b = *(const float4*)(wsrc + k0 + kq * 4);
            Bs[kq*4+0][row] = b.x; Bs[kq*4+1][row] = b.y;
            Bs[kq*4+2][row] = b.z; Bs[kq*4+3][row] = b.w;
        }
        __syncthreads();
#pragma unroll
        for (int kk = 0; kk < 32; kk++) {
            float4 aa = *(const float4*)&As[kk][ty * 4];
            float4 bb = *(const float4*)&Bs[kk][tx * 4];
            float av[4] = {aa.x, aa.y, aa.z, aa.w};
            float bv[4] = {bb.x, bb.y, bb.z, bb.w};
#pragma unroll
            for (int i = 0; i < 4; i++)
#pragma unroll
                for (int j = 0; j < 4; j++) acc[i][j] += av[i] * bv[j];
        }
        __syncthreads();
    }

#pragma unroll
    for (int i = 0; i < 4; i++) {
        int m = m0 + ty * 4 + i;
        float* orow = g_xg + (size_t)m * 4096 + n0 + tx * 4;
#pragma unroll
        for (int j = 0; j < 4; j++) {
            int n = n0 + tx * 4 + j;
            float bias = (n < 2048) ? (bihf[n] + bhhf[n])
                                    : (bihb[n - 2048] + bhhb[n - 2048]);
            orow[j] = acc[i][j] + bias;
        }
    }
}

// ---------------- kernel 2: persistent BiLSTM recurrence -------------------
// 128 CTAs (64/dir), 256 threads (8 warps) -> 256-reg budget, NO SPILLS.
// Warp w owns cell 8r+w entirely: lane l = gate (l>>3), k-slice [(l&7)*64,+64),
// weights f32x2 in REGISTERS. Per step: vote-poll 2 words/lane -> stage hsm ->
// ONE barrier -> per-warp dot + shfl reduce -> lane0 gates + release-publish.
__global__ void __launch_bounds__(REC_THREADS, 1)
lstm_rec(const float* __restrict__ whf, const float* __restrict__ whb,
         const float* __restrict__ h0, const float* __restrict__ c0)
{
    const int cta = blockIdx.x;       // 0..127
    const int d   = cta >> 6;
    const int r   = cta & 63;         // owns cells [8r, 8r+8)
    const int tid = threadIdx.x;
    const int w   = tid >> 5;         // warp 0..7 -> cell
    const int l   = tid & 31;
    const int gate = l >> 3;
    const int ks   = l & 7;           // k-slice id
    const int cell = (r << 3) + w;
    const int row  = gate * 512 + cell;

    const float* whh = d ? whb : whf;

    // ---- weights -> registers, packed f32x2 (one-time) ----
    unsigned long long W2[32];
    {
        const float2* wp = (const float2*)(whh + (size_t)row * 512 + ks * 64);
#pragma unroll
        for (int i = 0; i < 32; i++) {
            float2 v = wp[i];
            W2[i] = ((unsigned long long)__float_as_uint(v.y) << 32)
                  | (unsigned long long)__float_as_uint(v.x);
        }
    }

    __shared__ __align__(16) float hsm[2][512];   // parity-buffered staged h

    float cst = 0.f;
    if (l == 0) {
        cst = c0[d * 512 + cell];
        st_rel64(&g_hx[d][0][cell], pack_ht(h0[d * 512 + cell], 1u));
    }

    for (int s = 0; s < T_SEQ; s++) {
        const int t = d ? (T_SEQ - 1 - s) : s;

        // xg prefetch (independent of h); shared across each 8-lane group
        float xv = __ldcg(&g_xg[(size_t)t * 4096 + d * 2048 + row]);

        // ---- vote-poll: each lane owns 2 cells (tid, tid+256) ----
        {
            const unsigned want = (unsigned)(s + 1);
            const unsigned long long* hb = &g_hx[d][s & 1][0];
            unsigned long long v0 = 0, v1 = 0;
            bool d0 = false, d1 = false;
            for (;;) {
                if (!d0) { v0 = ld_acq64(hb + tid);       d0 = ((unsigned)(v0 >> 32) == want); }
                if (!d1) { v1 = ld_acq64(hb + 256 + tid); d1 = ((unsigned)(v1 >> 32) == want); }
                if (__all_sync(0xffffffffu, d0 && d1)) break;
            }
            hsm[s & 1][tid]       = __uint_as_float((unsigned)v0);
            hsm[s & 1][256 + tid] = __uint_as_float((unsigned)v1);
        }
        __syncthreads();

        // ---- dot: packed f32x2 FMA over this lane's 64-wide k-slice ----
        const ulonglong2* hv = (const ulonglong2*)&hsm[s & 1][ks << 6];
        unsigned long long a0 = 0ull, a1 = 0ull;
#pragma unroll
        for (int i = 0; i < 16; i++) {
            ulonglong2 h2 = hv[i];   // broadcast LDS within 8-lane group
            FMA2(a0, W2[2 * i],     h2.x, a0);
            FMA2(a1, W2[2 * i + 1], h2.y, a1);
        }
        float p0 = __uint_as_float((unsigned)a0) + __uint_as_float((unsigned)(a0 >> 32));
        float p1 = __uint_as_float((unsigned)a1) + __uint_as_float((unsigned)(a1 >> 32));
        float a = p0 + p1;
        // k-reduce across the 8-lane group (same tree: bit-identical)
        a += __shfl_xor_sync(0xffffffffu, a, 1);
        a += __shfl_xor_sync(0xffffffffu, a, 2);
        a += __shfl_xor_sync(0xffffffffu, a, 4);
        a += xv;
        // gather the four gate sums of this cell into lane 0
        float fg = __shfl_sync(0xffffffffu, a, 8);
        float gg = __shfl_sync(0xffffffffu, a, 16);
        float ov = __shfl_sync(0xffffffffu, a, 24);
        if (l == 0) {
            float iv = 1.f / (1.f + expf(-a));
            fg = 1.f / (1.f + expf(-fg));
            gg = tanhf(gg);
            ov = 1.f / (1.f + expf(-ov));
            cst = fg * cst + iv * gg;
            float hn = ov * tanhf(cst);
            st_rel64(&g_hx[d][(s + 1) & 1][cell], pack_ht(hn, (unsigned)(s + 2)));
            __stcg(&g_lstm[(size_t)t * 1024 + d * 512 + cell], hn);
        }
        // single barrier per step is sufficient: a warp can only restage
        // hsm[p] at step s+2 after all warps passed the barrier of step s+1,
        // which happens after every warp finished reading hsm[p] at step s.
    }
}

// ---------------- kernel 3: tag features -----------------------------------
__global__ void feats_k(const float* __restrict__ wtag, const float* __restrict__ btag)
{
    const int t = blockIdx.x;
    const int w = threadIdx.x >> 5;
    const int lane = threadIdx.x & 31;

    const float4* lx = (const float4*)(g_lstm + (size_t)t * 1024 + lane * 32);
    float4 X[8];
#pragma unroll
    for (int i = 0; i < 8; i++) X[i] = lx[i];

#pragma unroll
    for (int rep = 0; rep < 3; rep++) {
        int tag = w + rep * 8;
        const float4* wt = (const float4*)(wtag + (size_t)tag * 1024 + lane * 32);
        float a = 0.f;
#pragma unroll
        for (int i = 0; i < 8; i++) {
            float4 v = wt[i];
            a += X[i].x * v.x + X[i].y * v.y + X[i].z * v.z + X[i].w * v.w;
        }
#pragma unroll
        for (int o = 16; o; o >>= 1) a += __shfl_xor_sync(0xffffffffu, a, o);
        if (lane == 0) g_feats[t * TAGS + tag] = a + btag[tag];
    }
}

// ---------------- kernel 4: Viterbi (1 warp, bp in smem) -------------------
__global__ void viterbi_k(const float* __restrict__ trans, float* __restrict__ out,
                          int out_size)
{
    extern __shared__ unsigned char bp[];      // T_SEQ * TAGS bytes
    __shared__ float trs[TAGS * 25];
    __shared__ float stopr[TAGS];

    const int lane = threadIdx.x;
    for (int i = lane; i < TAGS * TAGS; i += 32) {
        int n = i / TAGS, p = i % TAGS;
        trs[n * 25 + p] = trans[i];
    }
    if (lane < TAGS) stopr[lane] = trans[STOP_T * TAGS + lane];
    __syncwarp();

    float fv = (lane == START_T) ? 0.f : NEGV;
    float feat = (lane < TAGS) ? g_feats[lane] : 0.f;

    for (int t = 0; t < T_SEQ; t++) {
        float nf = (lane < TAGS && t + 1 < T_SEQ) ? g_feats[(t + 1) * TAGS + lane] : 0.f;
        float best = -3.4e38f;
        int bi = 0;
#pragma unroll
        for (int p = 0; p < TAGS; p++) {
            float src = __shfl_sync(0xffffffffu, fv, p);
            float v = src + ((lane < TAGS) ? trs[lane * 25 + p] : 0.f);
            if (v > best) { best = v; bi = p; }
        }
        if (lane < TAGS) {
            fv = best + feat;
            bp[t * TAGS + lane] = (unsigned char)bi;
        } else {
            fv = NEGV;
        }
        feat = nf;
    }

    float ttl = (lane < TAGS) ? fv + stopr[lane] : -3.4e38f;
    float bv = ttl; int bi = lane;
#pragma unroll
    for (int o = 16; o; o >>= 1) {
        float ov = __shfl_down_sync(0xffffffffu, bv, o);
        int   oi = __shfl_down_sync(0xffffffffu, bi, o);
        if (ov > bv || (ov == bv && oi < bi)) { bv = ov; bi = oi; }
    }

    if (lane == 0) {
        float score = bv;
        int cur = bi;
        if (out_size >= T_SEQ + 1) {
            out[0] = score;
            float* path = out + 1;
            path[T_SEQ - 1] = (float)cur;
            for (int t = T_SEQ - 1; t >= 1; t--) {
                cur = bp[t * TAGS + cur];
                path[t - 1] = (float)cur;
            }
        } else if (out_size == T_SEQ) {
            out[T_SEQ - 1] = (float)cur;
            for (int t = T_SEQ - 1; t >= 1; t--) {
                cur = bp[t * TAGS + cur];
                out[t - 1] = (float)cur;
            }
        } else {
            out[0] = score;
        }
    }
}

// ---------------- launcher --------------------------------------------------
extern "C" void kernel_launch(void* const* d_in, const int* in_sizes, int n_in,
                              void* d_out, int out_size)
{
    const int*   sent  = (const int*)  d_in[0];
    const float* emb   = (const float*)d_in[1];
    const float* wihf  = (const float*)d_in[2];
    const float* whhf  = (const float*)d_in[3];
    const float* bihf  = (const float*)d_in[4];
    const float* bhhf  = (const float*)d_in[5];
    const float* wihb  = (const float*)d_in[6];
    const float* whhb  = (const float*)d_in[7];
    const float* bihb  = (const float*)d_in[8];
    const float* bhhb  = (const float*)d_in[9];
    const float* wtag  = (const float*)d_in[10];
    const float* btag  = (const float*)d_in[11];
    const float* trans = (const float*)d_in[12];
    const float* h0    = (const float*)d_in[13];
    const float* c0    = (const float*)d_in[14];
    float* out = (float*)d_out;

    proj_gemm<<<dim3(64, 64), 256>>>(sent, emb, wihf, wihb, bihf, bhhf, bihb, bhhb);
    lstm_rec<<<2 * NCTA_DIR, REC_THREADS>>>(whhf, whhb, h0, c0);
    feats_k<<<T_SEQ, 256>>>(wtag, btag);

    cudaFuncSetAttribute(viterbi_k, cudaFuncAttributeMaxDynamicSharedMemorySize,
                         T_SEQ * TAGS);
    viterbi_k<<<1, 32, T_SEQ * TAGS>>>(trans, out, out_size);
}

// round 15
// speedup vs baseline: 2.8936x; 2.2709x over previous
#include <cuda_runtime.h>
#include <cstdint>
#include <cmath>

#define T_SEQ   4096
#define TAGS    24
#define START_T 22
#define STOP_T  23
#define NEGV    (-10000.0f)

#define NCTA_DIR    64
#define REC_THREADS 256

// ---------------- scratch (device globals; no cudaMalloc allowed) ----------
__device__ float    g_lstm[(size_t)T_SEQ * 1024]; // [t][dir*512 + cell]
__device__ float    g_feats[T_SEQ * TAGS];
// h exchange: one 8B word per cell = (tag<<32 | fp32 bits). Tag==s+1 for the h
// that is INPUT to step s; double-buffered by step parity. STRONG acquire/
// release only (R12 lesson: weak 64b has no atomicity guarantee).
__device__ unsigned long long g_hx[2][2][512];    // [dir][parity][cell]

__device__ __forceinline__ unsigned long long ld_acq64(const unsigned long long* p)
{
    unsigned long long v;
    asm volatile("ld.acquire.gpu.global.u64 %0, [%1];" : "=l"(v) : "l"(p) : "memory");
    return v;
}
__device__ __forceinline__ void st_rel64(unsigned long long* p, unsigned long long v)
{
    asm volatile("st.release.gpu.global.u64 [%0], %1;" :: "l"(p), "l"(v) : "memory");
}
__device__ __forceinline__ unsigned long long pack_ht(float h, unsigned tag)
{
    return ((unsigned long long)tag << 32) | (unsigned long long)__float_as_uint(h);
}

#define FMA2(d, a, b, c) \
    asm("fma.rn.f32x2 %0, %1, %2, %3;" : "=l"(d) : "l"(a), "l"(b), "l"(c))

// ---------------- kernel 1: persistent BiLSTM recurrence (x-proj FUSED) ----
// 128 CTAs (64/dir), 256 threads (8 warps). R11 geometry (proven): warp w =
// k-slice [64w,64w+64); lane l = gate-row (gate l>>3, cell 8r+(l&7)). Both
// W_hh and W_ih slices live in REGISTERS (128 regs, budget 256, no spill).
// Per step: stage prefetched emb row -> x-dot (fills the producer-latency
// window) -> prefetch next emb row -> acquire-poll h -> h-dot -> sg (parity
// buffered) -> barrier -> warp0 reduce + bias + gates -> release-publish.
__global__ void __launch_bounds__(REC_THREADS, 1)
lstm_rec(const float* __restrict__ whf, const float* __restrict__ whb,
         const float* __restrict__ wif, const float* __restrict__ wib,
         const float* __restrict__ bihf, const float* __restrict__ bhhf,
         const float* __restrict__ bihb, const float* __restrict__ bhhb,
         const float* __restrict__ h0, const float* __restrict__ c0,
         const int* __restrict__ sent, const float* __restrict__ emb)
{
    const int cta = blockIdx.x;       // 0..127
    const int d   = cta >> 6;
    const int r   = cta & 63;         // owns cells [8r, 8r+8)
    const int tid = threadIdx.x;
    const int w   = tid >> 5;         // 0..7 k-slice (warp-uniform)
    const int l   = tid & 31;         // 0..31 gate-row
    const int gate = l >> 3;
    const int cell = (r << 3) + (l & 7);
    const int row  = gate * 512 + cell;

    const float* whh = d ? whb : whf;
    const float* wih = d ? wib : wif;

    // ---- weights -> registers, packed f32x2 (one-time) ----
    unsigned long long W2[32], WX2[32];
    {
        const float2* wp = (const float2*)(whh + (size_t)row * 512 + (w << 6));
        const float2* xp = (const float2*)(wih + (size_t)row * 512 + (w << 6));
#pragma unroll
        for (int i = 0; i < 32; i++) {
            float2 v = wp[i];
            W2[i] = ((unsigned long long)__float_as_uint(v.y) << 32)
                  | (unsigned long long)__float_as_uint(v.x);
            float2 u = xp[i];
            WX2[i] = ((unsigned long long)__float_as_uint(u.y) << 32)
                   | (unsigned long long)__float_as_uint(u.x);
        }
    }
    const float bias = d ? (bihb[row] + bhhb[row]) : (bihf[row] + bhhf[row]);

    __shared__ __align__(16) float  hsh[8][64];   // per-warp staged h slice
    __shared__ __align__(16) float4 xsm[8][16];   // per-warp staged emb slice
    __shared__ float sg[2][8][33];                // parity-buffered partials

    float cst = 0.f;
    if (tid < 8) {
        cst = c0[d * 512 + (r << 3) + tid];
        st_rel64(&g_hx[d][0][(r << 3) + tid],
                 pack_ht(h0[d * 512 + (r << 3) + tid], 1u));
    }

    // prefetch emb row for step 0
    float4 xf = {0.f, 0.f, 0.f, 0.f};
    {
        int t0 = d ? (T_SEQ - 1) : 0;
        int tok = __ldg(&sent[t0]);
        if (l < 16)
            xf = __ldg((const float4*)(emb + (size_t)tok * 512 + (w << 6)) + l);
    }

    for (int s = 0; s < T_SEQ; s++) {
        const int t = d ? (T_SEQ - 1 - s) : s;

        // ---- stage prefetched emb slice + x-dot (independent of h) ----
        if (l < 16) xsm[w][l] = xf;
        __syncwarp();
        const ulonglong2* xv2 = (const ulonglong2*)&xsm[w][0];
        unsigned long long ax0 = 0ull, ax1 = 0ull;
#pragma unroll
        for (int i = 0; i < 16; i++) {
            ulonglong2 x2 = xv2[i];   // broadcast LDS
            FMA2(ax0, WX2[2 * i],     x2.x, ax0);
            FMA2(ax1, WX2[2 * i + 1], x2.y, ax1);
        }

        // ---- prefetch next step's emb row (hidden behind poll + h-dot) ----
        if (s + 1 < T_SEQ) {
            int tn  = d ? (T_SEQ - 2 - s) : (s + 1);
            int tok = __ldg(&sent[tn]);
            if (l < 16)
                xf = __ldg((const float4*)(emb + (size_t)tok * 512 + (w << 6)) + l);
        }

        // ---- poll h (R11 verbatim): warp w owns cells [64w, 64w+64) ----
        {
            const unsigned want = (unsigned)(s + 1);
            const unsigned long long* hb = &g_hx[d][s & 1][w << 6];
            unsigned long long v0 = 0, v1 = 0;
            bool d0 = false, d1 = false;
            for (;;) {
                if (!d0) { v0 = ld_acq64(hb + l);      d0 = ((unsigned)(v0 >> 32) == want); }
                if (!d1) { v1 = ld_acq64(hb + 32 + l); d1 = ((unsigned)(v1 >> 32) == want); }
                if (__all_sync(0xffffffffu, d0 && d1)) break;
            }
            hsh[w][l]      = __uint_as_float((unsigned)v0);
            hsh[w][32 + l] = __uint_as_float((unsigned)v1);
        }
        __syncwarp();

        // ---- h-dot: packed f32x2 FMA over warp's 64-wide k-slice ----
        const ulonglong2* hv = (const ulonglong2*)&hsh[w][0];
        unsigned long long a0 = 0ull, a1 = 0ull;
#pragma unroll
        for (int i = 0; i < 16; i++) {
            ulonglong2 h2 = hv[i];   // broadcast LDS
            FMA2(a0, W2[2 * i],     h2.x, a0);
            FMA2(a1, W2[2 * i + 1], h2.y, a1);
        }
        float ph = (__uint_as_float((unsigned)a0) + __uint_as_float((unsigned)(a0 >> 32)))
                 + (__uint_as_float((unsigned)a1) + __uint_as_float((unsigned)(a1 >> 32)));
        float px = (__uint_as_float((unsigned)ax0) + __uint_as_float((unsigned)(ax0 >> 32)))
                 + (__uint_as_float((unsigned)ax1) + __uint_as_float((unsigned)(ax1 >> 32)));
        sg[s & 1][w][l] = ph + px;
        __syncthreads();

        if (tid < 32) {   // warp0: cross-warp reduce + bias + gates + publish
            const float (*sgp)[33] = sg[s & 1];
            float a = ((sgp[0][l] + sgp[1][l]) + (sgp[2][l] + sgp[3][l]))
                    + ((sgp[4][l] + sgp[5][l]) + (sgp[6][l] + sgp[7][l]));
            a += bias;
            float fg = __shfl_sync(0xffffffffu, a, (l & 7) + 8);
            float gg = __shfl_sync(0xffffffffu, a, (l & 7) + 16);
            float ov = __shfl_sync(0xffffffffu, a, (l & 7) + 24);
            if (l < 8) {
                float iv = 1.f / (1.f + expf(-a));
                fg = 1.f / (1.f + expf(-fg));
                gg = tanhf(gg);
                ov = 1.f / (1.f + expf(-ov));
                cst = fg * cst + iv * gg;
                float hn = ov * tanhf(cst);
                st_rel64(&g_hx[d][(s + 1) & 1][(r << 3) + l],
                         pack_ht(hn, (unsigned)(s + 2)));
                __stcg(&g_lstm[(size_t)t * 1024 + d * 512 + (r << 3) + l], hn);
            }
        }
        // sg is parity-buffered: step s+1 writes sg[(s+1)&1], so warp0's reads
        // of sg[s&1] can never be overwritten early. One barrier per step.
    }
}

// ---------------- kernel 2: tag features -----------------------------------
__global__ void feats_k(const float* __restrict__ wtag, const float* __restrict__ btag)
{
    const int t = blockIdx.x;
    const int w = threadIdx.x >> 5;
    const int lane = threadIdx.x & 31;

    const float4* lx = (const float4*)(g_lstm + (size_t)t * 1024 + lane * 32);
    float4 X[8];
#pragma unroll
    for (int i = 0; i < 8; i++) X[i] = lx[i];

#pragma unroll
    for (int rep = 0; rep < 3; rep++) {
        int tag = w + rep * 8;
        const float4* wt = (const float4*)(wtag + (size_t)tag * 1024 + lane * 32);
        float a = 0.f;
#pragma unroll
        for (int i = 0; i < 8; i++) {
            float4 v = wt[i];
            a += X[i].x * v.x + X[i].y * v.y + X[i].z * v.z + X[i].w * v.w;
        }
#pragma unroll
        for (int o = 16; o; o >>= 1) a += __shfl_xor_sync(0xffffffffu, a, o);
        if (lane == 0) g_feats[t * TAGS + tag] = a + btag[tag];
    }
}

// ---------------- kernel 3: Viterbi (1 warp, bp in smem) -------------------
__global__ void viterbi_k(const float* __restrict__ trans, float* __restrict__ out,
                          int out_size)
{
    extern __shared__ unsigned char bp[];      // T_SEQ * TAGS bytes
    __shared__ float trs[TAGS * 25];
    __shared__ float stopr[TAGS];

    const int lane = threadIdx.x;
    for (int i = lane; i < TAGS * TAGS; i += 32) {
        int n = i / TAGS, p = i % TAGS;
        trs[n * 25 + p] = trans[i];
    }
    if (lane < TAGS) stopr[lane] = trans[STOP_T * TAGS + lane];
    __syncwarp();

    float fv = (lane == START_T) ? 0.f : NEGV;
    float feat = (lane < TAGS) ? g_feats[lane] : 0.f;

    for (int t = 0; t < T_SEQ; t++) {
        float nf = (lane < TAGS && t + 1 < T_SEQ) ? g_feats[(t + 1) * TAGS + lane] : 0.f;
        float best = -3.4e38f;
        int bi = 0;
#pragma unroll
        for (int p = 0; p < TAGS; p++) {
            float src = __shfl_sync(0xffffffffu, fv, p);
            float v = src + ((lane < TAGS) ? trs[lane * 25 + p] : 0.f);
            if (v > best) { best = v; bi = p; }
        }
        if (lane < TAGS) {
            fv = best + feat;
            bp[t * TAGS + lane] = (unsigned char)bi;
        } else {
            fv = NEGV;
        }
        feat = nf;
    }

    float ttl = (lane < TAGS) ? fv + stopr[lane] : -3.4e38f;
    float bv = ttl; int bi = lane;
#pragma unroll
    for (int o = 16; o; o >>= 1) {
        float ov = __shfl_down_sync(0xffffffffu, bv, o);
        int   oi = __shfl_down_sync(0xffffffffu, bi, o);
        if (ov > bv || (ov == bv && oi < bi)) { bv = ov; bi = oi; }
    }

    if (lane == 0) {
        float score = bv;
        int cur = bi;
        if (out_size >= T_SEQ + 1) {
            out[0] = score;
            float* path = out + 1;
            path[T_SEQ - 1] = (float)cur;
            for (int t = T_SEQ - 1; t >= 1; t--) {
                cur = bp[t * TAGS + cur];
                path[t - 1] = (float)cur;
            }
        } else if (out_size == T_SEQ) {
            out[T_SEQ - 1] = (float)cur;
            for (int t = T_SEQ - 1; t >= 1; t--) {
                cur = bp[t * TAGS + cur];
                out[t - 1] = (float)cur;
            }
        } else {
            out[0] = score;
        }
    }
}

// ---------------- launcher --------------------------------------------------
extern "C" void kernel_launch(void* const* d_in, const int* in_sizes, int n_in,
                              void* d_out, int out_size)
{
    const int*   sent  = (const int*)  d_in[0];
    const float* emb   = (const float*)d_in[1];
    const float* wihf  = (const float*)d_in[2];
    const float* whhf  = (const float*)d_in[3];
    const float* bihf  = (const float*)d_in[4];
    const float* bhhf  = (const float*)d_in[5];
    const float* wihb  = (const float*)d_in[6];
    const float* whhb  = (const float*)d_in[7];
    const float* bihb  = (const float*)d_in[8];
    const float* bhhb  = (const float*)d_in[9];
    const float* wtag  = (const float*)d_in[10];
    const float* btag  = (const float*)d_in[11];
    const float* trans = (const float*)d_in[12];
    const float* h0    = (const float*)d_in[13];
    const float* c0    = (const float*)d_in[14];
    float* out = (float*)d_out;

    lstm_rec<<<2 * NCTA_DIR, REC_THREADS>>>(whhf, whhb, wihf, wihb,
                                            bihf, bhhf, bihb, bhhb,
                                            h0, c0, sent, emb);
    feats_k<<<T_SEQ, 256>>>(wtag, btag);

    cudaFuncSetAttribute(viterbi_k, cudaFuncAttributeMaxDynamicSharedMemorySize,
                         T_SEQ * TAGS);
    viterbi_k<<<1, 32, T_SEQ * TAGS>>>(trans, out, out_size);
}

// round 16
// speedup vs baseline: 2.9876x; 1.0325x over previous
#include <cuda_runtime.h>
#include <cstdint>
#include <cmath>

#define T_SEQ   4096
#define TAGS    24
#define START_T 22
#define STOP_T  23
#define NEGV    (-10000.0f)

#define NCTA_DIR    64
#define REC_THREADS 256

// ---------------- scratch (device globals; no cudaMalloc allowed) ----------
__device__ float    g_lstm[(size_t)T_SEQ * 1024]; // [t][dir*512 + cell]
__device__ float    g_feats[T_SEQ * TAGS];
// h exchange: one 8B word per cell = (tag<<32 | fp32 bits). Tag==s+1 for the h
// that is INPUT to step s; double-buffered by step parity. STRONG acquire/
// release only (R12 lesson: weak 64b has no atomicity guarantee).
__device__ unsigned long long g_hx[2][2][512];    // [dir][parity][cell]

__device__ __forceinline__ unsigned long long ld_acq64(const unsigned long long* p)
{
    unsigned long long v;
    asm volatile("ld.acquire.gpu.global.u64 %0, [%1];" : "=l"(v) : "l"(p) : "memory");
    return v;
}
__device__ __forceinline__ void st_rel64(unsigned long long* p, unsigned long long v)
{
    asm volatile("st.release.gpu.global.u64 [%0], %1;" :: "l"(p), "l"(v) : "memory");
}
__device__ __forceinline__ unsigned long long pack_ht(float h, unsigned tag)
{
    return ((unsigned long long)tag << 32) | (unsigned long long)__float_as_uint(h);
}

#define FMA2(d, a, b, c) \
    asm("fma.rn.f32x2 %0, %1, %2, %3;" : "=l"(d) : "l"(a), "l"(b), "l"(c))

// producer/consumer named barrier (id 1, full CTA = 256 threads)
#define BAR_ARRIVE() asm volatile("bar.arrive 1, 256;" ::: "memory")
#define BAR_SYNC()   asm volatile("bar.sync   1, 256;" ::: "memory")

// ---------------- kernel 1: persistent BiLSTM recurrence (x-proj fused) ----
// 128 CTAs (64/dir), 256 threads (8 warps). Warp w = k-slice [64w,64w+64);
// lane l = gate-row (gate l>>3, cell 8r+(l&7)). W_hh + W_ih in REGISTERS.
// Per step: stage emb slice -> ISSUE poll loads -> x-dot (overlaps poll RTT)
// -> prefetch next emb -> finish poll -> h-dot -> sg[parity] ->
//   warps1-7: bar.arrive, race ahead to next step
//   warp0:    bar.sync, reduce+bias, PARALLEL gate activations, publish.
__global__ void __launch_bounds__(REC_THREADS, 1)
lstm_rec(const float* __restrict__ whf, const float* __restrict__ whb,
         const float* __restrict__ wif, const float* __restrict__ wib,
         const float* __restrict__ bihf, const float* __restrict__ bhhf,
         const float* __restrict__ bihb, const float* __restrict__ bhhb,
         const float* __restrict__ h0, const float* __restrict__ c0,
         const int* __restrict__ sent, const float* __restrict__ emb)
{
    const int cta = blockIdx.x;       // 0..127
    const int d   = cta >> 6;
    const int r   = cta & 63;         // owns cells [8r, 8r+8)
    const int tid = threadIdx.x;
    const int w   = tid >> 5;         // 0..7 k-slice (warp-uniform)
    const int l   = tid & 31;         // 0..31 gate-row
    const int gate = l >> 3;
    const int cell = (r << 3) + (l & 7);
    const int row  = gate * 512 + cell;

    const float* whh = d ? whb : whf;
    const float* wih = d ? wib : wif;

    // ---- weights -> registers, packed f32x2 (one-time) ----
    unsigned long long W2[32], WX2[32];
    {
        const float2* wp = (const float2*)(whh + (size_t)row * 512 + (w << 6));
        const float2* xp = (const float2*)(wih + (size_t)row * 512 + (w << 6));
#pragma unroll
        for (int i = 0; i < 32; i++) {
            float2 v = wp[i];
            W2[i] = ((unsigned long long)__float_as_uint(v.y) << 32)
                  | (unsigned long long)__float_as_uint(v.x);
            float2 u = xp[i];
            WX2[i] = ((unsigned long long)__float_as_uint(u.y) << 32)
                   | (unsigned long long)__float_as_uint(u.x);
        }
    }
    const float bias = d ? (bihb[row] + bhhb[row]) : (bihf[row] + bhhf[row]);

    __shared__ __align__(16) float  hsh[8][64];   // per-warp staged h slice
    __shared__ __align__(16) float4 xsm[8][16];   // per-warp staged emb slice
    __shared__ float sg[2][8][33];                // parity-buffered partials

    float cst = 0.f;
    if (tid < 8) {
        cst = c0[d * 512 + (r << 3) + tid];
        st_rel64(&g_hx[d][0][(r << 3) + tid],
                 pack_ht(h0[d * 512 + (r << 3) + tid], 1u));
    }

    // prefetch emb row for step 0
    float4 xf = {0.f, 0.f, 0.f, 0.f};
    {
        int t0 = d ? (T_SEQ - 1) : 0;
        int tok = __ldg(&sent[t0]);
        if (l < 16)
            xf = __ldg((const float4*)(emb + (size_t)tok * 512 + (w << 6)) + l);
    }

    for (int s = 0; s < T_SEQ; s++) {
        const int t = d ? (T_SEQ - 1 - s) : s;

        // ---- stage prefetched emb slice ----
        if (l < 16) xsm[w][l] = xf;
        __syncwarp();

        // ---- issue poll loads EARLY (first RTT overlaps x-dot below) ----
        const unsigned want = (unsigned)(s + 1);
        const unsigned long long* hb = &g_hx[d][s & 1][w << 6];
        unsigned long long v0 = ld_acq64(hb + l);
        unsigned long long v1 = ld_acq64(hb + 32 + l);

        // ---- x-dot (independent of h) ----
        const ulonglong2* xv2 = (const ulonglong2*)&xsm[w][0];
        unsigned long long ax0 = 0ull, ax1 = 0ull;
#pragma unroll
        for (int i = 0; i < 16; i++) {
            ulonglong2 x2 = xv2[i];   // broadcast LDS
            FMA2(ax0, WX2[2 * i],     x2.x, ax0);
            FMA2(ax1, WX2[2 * i + 1], x2.y, ax1);
        }

        // ---- prefetch next step's emb row (hidden behind poll) ----
        if (s + 1 < T_SEQ) {
            int tn  = d ? (T_SEQ - 2 - s) : (s + 1);
            int tok = __ldg(&sent[tn]);
            if (l < 16)
                xf = __ldg((const float4*)(emb + (size_t)tok * 512 + (w << 6)) + l);
        }

        // ---- finish poll ----
        {
            bool d0 = ((unsigned)(v0 >> 32) == want);
            bool d1 = ((unsigned)(v1 >> 32) == want);
            while (!__all_sync(0xffffffffu, d0 && d1)) {
                if (!d0) { v0 = ld_acq64(hb + l);      d0 = ((unsigned)(v0 >> 32) == want); }
                if (!d1) { v1 = ld_acq64(hb + 32 + l); d1 = ((unsigned)(v1 >> 32) == want); }
            }
            hsh[w][l]      = __uint_as_float((unsigned)v0);
            hsh[w][32 + l] = __uint_as_float((unsigned)v1);
        }
        __syncwarp();

        // ---- h-dot: packed f32x2 FMA over warp's 64-wide k-slice ----
        const ulonglong2* hv = (const ulonglong2*)&hsh[w][0];
        unsigned long long a0 = 0ull, a1 = 0ull;
#pragma unroll
        for (int i = 0; i < 16; i++) {
            ulonglong2 h2 = hv[i];   // broadcast LDS
            FMA2(a0, W2[2 * i],     h2.x, a0);
            FMA2(a1, W2[2 * i + 1], h2.y, a1);
        }
        float ph = (__uint_as_float((unsigned)a0) + __uint_as_float((unsigned)(a0 >> 32)))
                 + (__uint_as_float((unsigned)a1) + __uint_as_float((unsigned)(a1 >> 32)));
        float px = (__uint_as_float((unsigned)ax0) + __uint_as_float((unsigned)(ax0 >> 32)))
                 + (__uint_as_float((unsigned)ax1) + __uint_as_float((unsigned)(ax1 >> 32)));
        sg[s & 1][w][l] = ph + px;

        if (tid >= 32) {
            // producers of partials only: signal and race ahead. Safe: sg is
            // parity-buffered, and 2-phase skew is impossible (re-writing
            // sg[s&1] at s+2 needs tag s+3, which transitively requires THIS
            // CTA's publish of tag s+2, i.e. warp0 already consumed sg[s&1]).
            BAR_ARRIVE();
        } else {
            BAR_SYNC();   // wait for all 8 partials (fence included)
            const float (*sgp)[33] = sg[s & 1];
            float a = ((sgp[0][l] + sgp[1][l]) + (sgp[2][l] + sgp[3][l]))
                    + ((sgp[4][l] + sgp[5][l]) + (sgp[6][l] + sgp[7][l]));
            a += bias;
            // parallel activations: every lane transforms its own gate value
            // (bit-identical: same inputs, same functions as the serial form)
            float act = (gate == 2) ? tanhf(a) : (1.f / (1.f + expf(-a)));
            float fg = __shfl_sync(0xffffffffu, act, (l & 7) + 8);
            float gg = __shfl_sync(0xffffffffu, act, (l & 7) + 16);
            float ov = __shfl_sync(0xffffffffu, act, (l & 7) + 24);
            if (l < 8) {
                cst = fg * cst + act * gg;          // act = sigmoid(i) here
                float hn = ov * tanhf(cst);
                st_rel64(&g_hx[d][(s + 1) & 1][(r << 3) + l],
                         pack_ht(hn, (unsigned)(s + 2)));
                __stcg(&g_lstm[(size_t)t * 1024 + d * 512 + (r << 3) + l], hn);
            }
        }
    }
}

// ---------------- kernel 2: tag features -----------------------------------
__global__ void feats_k(const float* __restrict__ wtag, const float* __restrict__ btag)
{
    const int t = blockIdx.x;
    const int w = threadIdx.x >> 5;
    const int lane = threadIdx.x & 31;

    const float4* lx = (const float4*)(g_lstm + (size_t)t * 1024 + lane * 32);
    float4 X[8];
#pragma unroll
    for (int i = 0; i < 8; i++) X[i] = lx[i];

#pragma unroll
    for (int rep = 0; rep < 3; rep++) {
        int tag = w + rep * 8;
        const float4* wt = (const float4*)(wtag + (size_t)tag * 1024 + lane * 32);
        float a = 0.f;
#pragma unroll
        for (int i = 0; i < 8; i++) {
            float4 v = wt[i];
            a += X[i].x * v.x + X[i].y * v.y + X[i].z * v.z + X[i].w * v.w;
        }
#pragma unroll
        for (int o = 16; o; o >>= 1) a += __shfl_xor_sync(0xffffffffu, a, o);
        if (lane == 0) g_feats[t * TAGS + tag] = a + btag[tag];
    }
}

// ---------------- kernel 3: Viterbi (1 warp, bp in smem) -------------------
__global__ void viterbi_k(const float* __restrict__ trans, float* __restrict__ out,
                          int out_size)
{
    extern __shared__ unsigned char bp[];      // T_SEQ * TAGS bytes
    __shared__ float trs[TAGS * 25];
    __shared__ float stopr[TAGS];

    const int lane = threadIdx.x;
    for (int i = lane; i < TAGS * TAGS; i += 32) {
        int n = i / TAGS, p = i % TAGS;
        trs[n * 25 + p] = trans[i];
    }
    if (lane < TAGS) stopr[lane] = trans[STOP_T * TAGS + lane];
    __syncwarp();

    float fv = (lane == START_T) ? 0.f : NEGV;
    float feat = (lane < TAGS) ? g_feats[lane] : 0.f;

    for (int t = 0; t < T_SEQ; t++) {
        float nf = (lane < TAGS && t + 1 < T_SEQ) ? g_feats[(t + 1) * TAGS + lane] : 0.f;
        float best = -3.4e38f;
        int bi = 0;
#pragma unroll
        for (int p = 0; p < TAGS; p++) {
            float src = __shfl_sync(0xffffffffu, fv, p);
            float v = src + ((lane < TAGS) ? trs[lane * 25 + p] : 0.f);
            if (v > best) { best = v; bi = p; }
        }
        if (lane < TAGS) {
            fv = best + feat;
            bp[t * TAGS + lane] = (unsigned char)bi;
        } else {
            fv = NEGV;
        }
        feat = nf;
    }

    float ttl = (lane < TAGS) ? fv + stopr[lane] : -3.4e38f;
    float bv = ttl; int bi = lane;
#pragma unroll
    for (int o = 16; o; o >>= 1) {
        float ov = __shfl_down_sync(0xffffffffu, bv, o);
        int   oi = __shfl_down_sync(0xffffffffu, bi, o);
        if (ov > bv || (ov == bv && oi < bi)) { bv = ov; bi = oi; }
    }

    if (lane == 0) {
        float score = bv;
        int cur = bi;
        if (out_size >= T_SEQ + 1) {
            out[0] = score;
            float* path = out + 1;
            path[T_SEQ - 1] = (float)cur;
            for (int t = T_SEQ - 1; t >= 1; t--) {
                cur = bp[t * TAGS + cur];
                path[t - 1] = (float)cur;
            }
        } else if (out_size == T_SEQ) {
            out[T_SEQ - 1] = (float)cur;
            for (int t = T_SEQ - 1; t >= 1; t--) {
                cur = bp[t * TAGS + cur];
                out[t - 1] = (float)cur;
            }
        } else {
            out[0] = score;
        }
    }
}

// ---------------- launcher --------------------------------------------------
extern "C" void kernel_launch(void* const* d_in, const int* in_sizes, int n_in,
                              void* d_out, int out_size)
{
    const int*   sent  = (const int*)  d_in[0];
    const float* emb   = (const float*)d_in[1];
    const float* wihf  = (const float*)d_in[2];
    const float* whhf  = (const float*)d_in[3];
    const float* bihf  = (const float*)d_in[4];
    const float* bhhf  = (const float*)d_in[5];
    const float* wihb  = (const float*)d_in[6];
    const float* whhb  = (const float*)d_in[7];
    const float* bihb  = (const float*)d_in[8];
    const float* bhhb  = (const float*)d_in[9];
    const float* wtag  = (const float*)d_in[10];
    const float* btag  = (const float*)d_in[11];
    const float* trans = (const float*)d_in[12];
    const float* h0    = (const float*)d_in[13];
    const float* c0    = (const float*)d_in[14];
    float* out = (float*)d_out;

    lstm_rec<<<2 * NCTA_DIR, REC_THREADS>>>(whhf, whhb, wihf, wihb,
                                            bihf, bhhf, bihb, bhhb,
                                            h0, c0, sent, emb);
    feats_k<<<T_SEQ, 256>>>(wtag, btag);

    cudaFuncSetAttribute(viterbi_k, cudaFuncAttributeMaxDynamicSharedMemorySize,
                         T_SEQ * TAGS);
    viterbi_k<<<1, 32, T_SEQ * TAGS>>>(trans, out, out_size);
}